// round 8
// baseline (speedup 1.0000x reference)
#include <cuda_runtime.h>

// Problem constants
constexpr int kB = 512;   // batch
constexpr int kL = 128;   // seq len
constexpr int kD = 128;   // model dim
// H = 4 heads of 32
constexpr int kTC = 32;   // timesteps per chunk
constexpr int kNC = kL / kTC;  // 4 chunks

// Scratch (device globals: allocation-free rule)
__device__ float    g_x [kB * kL * kD];               // residual stream, [b][t][d]
__device__ unsigned g_xn[kB * kL * kD];               // LN output, tf32 bit patterns
__device__ float    g_h [kB * kL * kD];               // raw scan output h
__device__ float    g_pre[(size_t)kL * kB * 4 * kD];  // gate preacts, [t][b][g][d]
__device__ unsigned g_Wt[2 * 4 * kD * kD];            // W rounded to tf32
__device__ float    g_state[4][kB][kD];               // scan state h,c,n,m between chunks

typedef unsigned long long ull;

__device__ __forceinline__ ull pack2(float lo, float hi) {
    ull r; asm("mov.b64 %0,{%1,%2};" : "=l"(r) : "f"(lo), "f"(hi)); return r;
}
__device__ __forceinline__ void unpack2(ull v, float& lo, float& hi) {
    asm("mov.b64 {%0,%1},%2;" : "=f"(lo), "=f"(hi) : "l"(v));
}
__device__ __forceinline__ ull ffma2(ull a, ull b, ull c) {
    ull d; asm("fma.rn.f32x2 %0,%1,%2,%3;" : "=l"(d) : "l"(a), "l"(b), "l"(c)); return d;
}
__device__ __forceinline__ float tanh_fast(float x) {
    float y; asm("tanh.approx.f32 %0,%1;" : "=f"(y) : "f"(x)); return y;
}
__device__ __forceinline__ unsigned to_tf32(float f) {
    unsigned u; asm("cvt.rna.tf32.f32 %0, %1;" : "=r"(u) : "f"(f)); return u;
}

__device__ __forceinline__ void cp_async16(unsigned smem, const void* gptr) {
    asm volatile("cp.async.cg.shared.global [%0], [%1], 16;" :: "r"(smem), "l"(gptr));
}
__device__ __forceinline__ void cp_commit() {
    asm volatile("cp.async.commit_group;");
}
template<int N>
__device__ __forceinline__ void cp_wait() {
    asm volatile("cp.async.wait_group %0;" :: "n"(N));
}

// ---------------------------------------------------------------------------
// W -> tf32 pre-round (both layers, once per launch)
// ---------------------------------------------------------------------------
__global__ void k_wcvt(const float* __restrict__ Wg) {
    int i = blockIdx.x * 256 + threadIdx.x;
    #pragma unroll
    for (int j = 0; j < 4; j++) {
        int e = i * 4 + j;
        g_Wt[e] = to_tf32(__ldg(&Wg[e]));
    }
}

// ---------------------------------------------------------------------------
// Fused embedding gather + LayerNorm(layer0). One warp per row of 128.
// ---------------------------------------------------------------------------
__global__ void k_embed_ln(const int* __restrict__ ids, const float4* __restrict__ emb,
                           const float* __restrict__ w, const float* __restrict__ bb) {
    int t    = blockIdx.x * 256 + threadIdx.x;
    int row  = t >> 5;
    int lane = t & 31;
    int id   = __ldg(&ids[row]);
    float4 v = emb[(size_t)id * 32 + lane];
    ((float4*)g_x)[(size_t)row * 32 + lane] = v;
    float s = v.x + v.y + v.z + v.w;
    float q = v.x*v.x + v.y*v.y + v.z*v.z + v.w*v.w;
    #pragma unroll
    for (int o = 16; o; o >>= 1) {
        s += __shfl_xor_sync(0xffffffffu, s, o);
        q += __shfl_xor_sync(0xffffffffu, q, o);
    }
    float mu  = s * (1.f / 128.f);
    float var = fmaxf(q * (1.f / 128.f) - mu * mu, 0.f);
    float rs  = rsqrtf(var + 1e-5f);
    float4 wv = ((const float4*)w)[lane];
    float4 bv = ((const float4*)bb)[lane];
    uint4 o4;
    o4.x = to_tf32((v.x - mu) * rs * wv.x + bv.x);
    o4.y = to_tf32((v.y - mu) * rs * wv.y + bv.y);
    o4.z = to_tf32((v.z - mu) * rs * wv.z + bv.z);
    o4.w = to_tf32((v.w - mu) * rs * wv.w + bv.w);
    ((uint4*)g_xn)[(size_t)row * 32 + lane] = o4;
}

// ---------------------------------------------------------------------------
// Fused GroupNorm + residual (+ optional LayerNorm->tf32 for next layer).
// ---------------------------------------------------------------------------
template<bool DO_LN>
__global__ void k_gn(const float* __restrict__ gnw,
                     const float* __restrict__ lnw, const float* __restrict__ lnb) {
    const unsigned FULL = 0xffffffffu;
    int t    = blockIdx.x * 256 + threadIdx.x;
    int row  = t >> 5;
    int lane = t & 31;
    float4 hv = ((const float4*)g_h)[(size_t)row * 32 + lane];
    float4 xv = ((const float4*)g_x)[(size_t)row * 32 + lane];
    float s = hv.x + hv.y + hv.z + hv.w;
    float q = hv.x*hv.x + hv.y*hv.y + hv.z*hv.z + hv.w*hv.w;
    #pragma unroll
    for (int o = 1; o < 8; o <<= 1) {
        s += __shfl_xor_sync(FULL, s, o);
        q += __shfl_xor_sync(FULL, q, o);
    }
    float mu  = s * (1.f / 32.f);
    float var = fmaxf(q * (1.f / 32.f) - mu * mu, 0.f);
    float rs  = rsqrtf(var + 1e-5f);
    float4 gw = ((const float4*)gnw)[lane];
    float4 xp;
    xp.x = xv.x + (hv.x - mu) * rs * gw.x;
    xp.y = xv.y + (hv.y - mu) * rs * gw.y;
    xp.z = xv.z + (hv.z - mu) * rs * gw.z;
    xp.w = xv.w + (hv.w - mu) * rs * gw.w;
    ((float4*)g_x)[(size_t)row * 32 + lane] = xp;

    if (DO_LN) {
        float s2 = xp.x + xp.y + xp.z + xp.w;
        float q2 = xp.x*xp.x + xp.y*xp.y + xp.z*xp.z + xp.w*xp.w;
        #pragma unroll
        for (int o = 16; o; o >>= 1) {
            s2 += __shfl_xor_sync(FULL, s2, o);
            q2 += __shfl_xor_sync(FULL, q2, o);
        }
        float mu2  = s2 * (1.f / 128.f);
        float var2 = fmaxf(q2 * (1.f / 128.f) - mu2 * mu2, 0.f);
        float rs2  = rsqrtf(var2 + 1e-5f);
        float4 wv = ((const float4*)lnw)[lane];
        float4 bv = ((const float4*)lnb)[lane];
        uint4 o4;
        o4.x = to_tf32((xp.x - mu2) * rs2 * wv.x + bv.x);
        o4.y = to_tf32((xp.y - mu2) * rs2 * wv.y + bv.y);
        o4.z = to_tf32((xp.z - mu2) * rs2 * wv.z + bv.z);
        o4.w = to_tf32((xp.w - mu2) * rs2 * wv.w + bv.w);
        ((uint4*)g_xn)[(size_t)row * 32 + lane] = o4;
    }
}

// ---------------------------------------------------------------------------
// tf32 GEMM chunk, 128 threads (2x2 warps, 64x64 warp tiles) so it can
// co-reside with a scan CTA on the same SM (regs ~25K + scan ~27K < 64K).
// Tile = 128 rows = 4 batches x 32 timesteps. B resident; A double-buffered.
// grid (4, 32): bn = gate, bmg = group of 4 tiles.
// ---------------------------------------------------------------------------
__global__ void __launch_bounds__(128) k_gemm_c(int layer, int chunk,
                                                const float* __restrict__ bias) {
    constexpr int STR = 132;                 // padded smem stride (words)
    extern __shared__ unsigned sh[];
    unsigned* Bs = sh;                       // [128][132]
    unsigned* As0 = sh + 128 * STR;          // double buffer
    unsigned* As1 = As0 + 128 * STR;

    int tid = threadIdx.x;
    int bn  = blockIdx.x;                    // gate (fastest -> A dedup in L2)
    int bmg = blockIdx.y;                    // group of 4 tiles

    const unsigned* Wg = g_Wt + (size_t)(layer * 4 + bn) * 128 * 128;
    unsigned As0_u = (unsigned)__cvta_generic_to_shared(As0);
    unsigned As1_u = (unsigned)__cvta_generic_to_shared(As1);
    unsigned Bs_u  = (unsigned)__cvta_generic_to_shared(Bs);
    int l0 = chunk * kTC;

    // A row for tile rt, local row rr:  b = 4*rt + rr/32 ; l = l0 + rr%32
    auto issueA = [&](unsigned dst, int rt) {
        #pragma unroll
        for (int i = 0; i < 32; i++) {
            int e = i * 128 + tid, rr = e >> 5, c4 = e & 31;
            int arow = (4 * rt + (rr >> 5)) * 128 + l0 + (rr & 31);
            cp_async16(dst + (rr * STR + c4 * 4) * 4, g_xn + (size_t)arow * 128 + c4 * 4);
        }
    };

    // issue B + A0
    #pragma unroll
    for (int i = 0; i < 32; i++) {
        int e = i * 128 + tid, rr = e >> 5, c4 = e & 31;
        cp_async16(Bs_u + (rr * STR + c4 * 4) * 4, Wg + rr * 128 + c4 * 4);
    }
    issueA(As0_u, bmg * 4 + 0);
    cp_commit();
    issueA(As1_u, bmg * 4 + 1);
    cp_commit();

    int warp = tid >> 5, lane = tid & 31;
    int wm = warp >> 1, wn = warp & 1;       // 2x2 warp grid, 64x64 tiles
    int gid = lane >> 2, tg = lane & 3;

    float bz[8][2];
    #pragma unroll
    for (int j = 0; j < 8; j++) {
        int col = bn * 128 + wn * 64 + j * 8 + tg * 2;
        bz[j][0] = __ldg(&bias[col]);
        bz[j][1] = __ldg(&bias[col + 1]);
    }

    #pragma unroll
    for (int it = 0; it < 4; it++) {
        unsigned* As = (it & 1) ? As1 : As0;
        if (it < 3) cp_wait<1>(); else cp_wait<0>();
        __syncthreads();

        float acc[4][8][4];
        #pragma unroll
        for (int i = 0; i < 4; i++)
            #pragma unroll
            for (int j = 0; j < 8; j++)
                #pragma unroll
                for (int c = 0; c < 4; c++) acc[i][j][c] = 0.f;

        #pragma unroll
        for (int ks = 0; ks < 16; ks++) {
            int k0 = ks * 8 + tg;
            unsigned a[4][4], bf[8][2];
            #pragma unroll
            for (int i = 0; i < 4; i++) {
                int r0 = wm * 64 + i * 16 + gid;
                a[i][0] = As[r0 * STR + k0];
                a[i][1] = As[(r0 + 8) * STR + k0];
                a[i][2] = As[r0 * STR + k0 + 4];
                a[i][3] = As[(r0 + 8) * STR + k0 + 4];
            }
            #pragma unroll
            for (int j = 0; j < 8; j++) {
                int n0 = wn * 64 + j * 8 + gid;
                bf[j][0] = Bs[n0 * STR + k0];
                bf[j][1] = Bs[n0 * STR + k0 + 4];
            }
            #pragma unroll
            for (int i = 0; i < 4; i++)
                #pragma unroll
                for (int j = 0; j < 8; j++)
                    asm volatile(
                        "mma.sync.aligned.m16n8k8.row.col.f32.tf32.tf32.f32 "
                        "{%0,%1,%2,%3}, {%4,%5,%6,%7}, {%8,%9}, {%0,%1,%2,%3};"
                        : "+f"(acc[i][j][0]), "+f"(acc[i][j][1]),
                          "+f"(acc[i][j][2]), "+f"(acc[i][j][3])
                        : "r"(a[i][0]), "r"(a[i][1]), "r"(a[i][2]), "r"(a[i][3]),
                          "r"(bf[j][0]), "r"(bf[j][1]));
        }
        __syncthreads();

        if (it + 2 < 4) {
            unsigned dst = (it & 1) ? As1_u : As0_u;
            issueA(dst, bmg * 4 + it + 2);
            cp_commit();
        }

        // epilogue: local row lr -> b = 4*rt + lr/32, l = l0 + lr%32
        int rt = bmg * 4 + it;
        #pragma unroll
        for (int i = 0; i < 4; i++) {
            int lra = wm * 64 + i * 16 + gid;
            int lrb = lra + 8;
            int ba = 4 * rt + (lra >> 5), la = l0 + (lra & 31);
            int bb2 = 4 * rt + (lrb >> 5), lb = l0 + (lrb & 31);
            float* outa = g_pre + ((size_t)la * 512 + ba) * 512;
            float* outb = g_pre + ((size_t)lb * 512 + bb2) * 512;
            #pragma unroll
            for (int j = 0; j < 8; j++) {
                int col = bn * 128 + wn * 64 + j * 8 + tg * 2;
                *(float2*)&outa[col] = make_float2(acc[i][j][0] + bz[j][0], acc[i][j][1] + bz[j][1]);
                *(float2*)&outb[col] = make_float2(acc[i][j][2] + bz[j][0], acc[i][j][3] + bz[j][1]);
            }
        }
    }
}

// ---------------------------------------------------------------------------
// sLSTM gate math: 5 MUFU (3 ex2 + tanh + rcp)
// ---------------------------------------------------------------------------
__device__ __forceinline__ void gate_step(float ai, float af, float az, float ao,
                                          float& h, float& c, float& n, float& m) {
    float fm = af + m;
    float mn = fmaxf(fm, ai);
    float iv = __expf(ai - mn);
    float fv = __expf(fm - mn);
    float th = tanh_fast(az);
    c = fmaf(fv, c, iv * th);
    n = fmaf(fv, n, iv);
    float eo = __expf(-ao);                   // h = sigmoid(ao) * c / n
    float denom = fmaf(n, eo, n);             //   = c / (n * (1 + e^-ao))
    h = __fdividef(c, denom);
    m = mn;
}

// ---------------------------------------------------------------------------
// Recurrent sLSTM scan chunk: 128 threads (warp = head), ILP-4 batches per
// thread, grid 128 (one CTA per SM -> room for a co-resident GEMM CTA).
// Barrier-free: h broadcast via warp-local smem. State in g_state.
// ---------------------------------------------------------------------------
template<bool FIRST>
__global__ void __launch_bounds__(128, 1) k_scan_c(const float* __restrict__ R, int chunk) {
    __shared__ float shh[2][4][4][32];        // [slot][batch][head][lane]

    int o    = threadIdx.x;                   // output dim
    int hh   = o >> 5;                        // head
    int lane = o & 31;

    int b0 = blockIdx.x * 4;                  // 4 batches per CTA

    // Rr2[g*16+dp] = ( R[g][hh][2dp][lane], R[g][hh][2dp+1][lane] )
    ull Rr2[64];
    #pragma unroll
    for (int g = 0; g < 4; g++)
        #pragma unroll
        for (int dp = 0; dp < 16; dp++) {
            float r0 = __ldg(&R[((g * 4 + hh) * 32 + 2 * dp)     * 32 + lane]);
            float r1 = __ldg(&R[((g * 4 + hh) * 32 + 2 * dp + 1) * 32 + lane]);
            Rr2[g * 16 + dp] = pack2(r0, r1);
        }

    float h[4], c[4], n[4], m[4];
    #pragma unroll
    for (int bi = 0; bi < 4; bi++) {
        if (FIRST) {
            h[bi] = c[bi] = n[bi] = m[bi] = 0.f;
        } else {
            h[bi] = g_state[0][b0 + bi][o]; c[bi] = g_state[1][b0 + bi][o];
            n[bi] = g_state[2][b0 + bi][o]; m[bi] = g_state[3][b0 + bi][o];
        }
    }

    const float* pp[4];
    float* ho[4];
    float p[4][4];
    #pragma unroll
    for (int bi = 0; bi < 4; bi++) {
        pp[bi] = g_pre + (size_t)(chunk * kTC) * (kB * 512) + (size_t)(b0 + bi) * 512 + o;
        ho[bi] = g_h + (size_t)(b0 + bi) * kL * kD + (size_t)(chunk * kTC) * kD + o;
        p[bi][0] = pp[bi][0];   p[bi][1] = pp[bi][128];
        p[bi][2] = pp[bi][256]; p[bi][3] = pp[bi][384];
    }

    for (int t = 0; t < kTC; t++) {
        int s = t & 1;
        #pragma unroll
        for (int bi = 0; bi < 4; bi++) shh[s][bi][hh][lane] = h[bi];
        __syncwarp();

        ull acc[4][4];                        // [batch][gate]
        #pragma unroll
        for (int bi = 0; bi < 4; bi++)
            #pragma unroll
            for (int g = 0; g < 4; g++) acc[bi][g] = 0;

        #pragma unroll
        for (int j = 0; j < 8; j++) {
            int dp = 2 * j;
            #pragma unroll
            for (int bi = 0; bi < 4; bi++) {
                float4 v = ((const float4*)shh[s][bi][hh])[j];
                ull v01 = pack2(v.x, v.y), v23 = pack2(v.z, v.w);
                #pragma unroll
                for (int g = 0; g < 4; g++) {
                    acc[bi][g] = ffma2(v01, Rr2[g * 16 + dp],     acc[bi][g]);
                    acc[bi][g] = ffma2(v23, Rr2[g * 16 + dp + 1], acc[bi][g]);
                }
            }
        }

        float pre[4][4];
        #pragma unroll
        for (int bi = 0; bi < 4; bi++)
            #pragma unroll
            for (int g = 0; g < 4; g++) pre[bi][g] = p[bi][g];

        if (t + 1 < kTC) {
            #pragma unroll
            for (int bi = 0; bi < 4; bi++) {
                const float* pn = pp[bi] + (size_t)(t + 1) * (kB * 512);
                p[bi][0] = pn[0];   p[bi][1] = pn[128];
                p[bi][2] = pn[256]; p[bi][3] = pn[384];
            }
        }

        #pragma unroll
        for (int bi = 0; bi < 4; bi++) {
            float g4[4];
            #pragma unroll
            for (int g = 0; g < 4; g++) {
                float lo, hi;
                unpack2(acc[bi][g], lo, hi);
                g4[g] = lo + hi + pre[bi][g];
            }
            gate_step(g4[0], g4[1], g4[2], g4[3], h[bi], c[bi], n[bi], m[bi]);
            ho[bi][(size_t)t * kD] = h[bi];
        }
    }

    #pragma unroll
    for (int bi = 0; bi < 4; bi++) {
        g_state[0][b0 + bi][o] = h[bi]; g_state[1][b0 + bi][o] = c[bi];
        g_state[2][b0 + bi][o] = n[bi]; g_state[3][b0 + bi][o] = m[bi];
    }
}

// ---------------------------------------------------------------------------
// Head: mean over time, then 128->64 ReLU MLP, then 64->2
// ---------------------------------------------------------------------------
__global__ void k_head(const float* __restrict__ w1, const float* __restrict__ b1,
                       const float* __restrict__ w2, const float* __restrict__ b2,
                       float* __restrict__ out) {
    __shared__ float pooled[128];
    __shared__ float hid[64];
    int b = blockIdx.x, o = threadIdx.x;
    const float* xb = g_x + (size_t)b * kL * kD + o;
    float s = 0.f;
    #pragma unroll 8
    for (int t = 0; t < kL; t++) s += xb[(size_t)t * kD];
    pooled[o] = s * (1.f / 128.f);
    __syncthreads();
    if (o < 64) {
        float a = __ldg(&b1[o]);
        const float* wr = w1 + o * 128;
        #pragma unroll
        for (int d = 0; d < 128; d++) a = fmaf(pooled[d], __ldg(&wr[d]), a);
        hid[o] = fmaxf(a, 0.f);
    }
    __syncthreads();
    if (o < 2) {
        float a = __ldg(&b2[o]);
        const float* wr = w2 + o * 64;
        #pragma unroll
        for (int j = 0; j < 64; j++) a = fmaf(hid[j], __ldg(&wr[j]), a);
        out[b * 2 + o] = a;
    }
}

// ---------------------------------------------------------------------------
extern "C" void kernel_launch(void* const* d_in, const int* in_sizes, int n_in,
                              void* d_out, int out_size) {
    const int*   ids  = (const int*)  d_in[0];
    const float* emb  = (const float*)d_in[1];
    const float* ln_w = (const float*)d_in[2];
    const float* ln_b = (const float*)d_in[3];
    const float* Wg   = (const float*)d_in[4];
    const float* Rg   = (const float*)d_in[5];
    const float* bg   = (const float*)d_in[6];
    const float* gn_w = (const float*)d_in[7];
    const float* w1   = (const float*)d_in[8];
    const float* b1   = (const float*)d_in[9];
    const float* w2   = (const float*)d_in[10];
    const float* b2   = (const float*)d_in[11];
    float* out = (float*)d_out;

    // one-time stream/event creation (host resources only; no device memory)
    static cudaStream_t s1 = nullptr;
    static cudaEvent_t evXn[2];
    static cudaEvent_t evG[2][kNC];
    if (!s1) {
        cudaStreamCreateWithFlags(&s1, cudaStreamNonBlocking);
        for (int l = 0; l < 2; l++) {
            cudaEventCreateWithFlags(&evXn[l], cudaEventDisableTiming);
            for (int c = 0; c < kNC; c++)
                cudaEventCreateWithFlags(&evG[l][c], cudaEventDisableTiming);
        }
    }

    constexpr int GEMM_SMEM = 3 * 128 * 132 * 4;   // 202752 B
    cudaFuncSetAttribute(k_gemm_c, cudaFuncAttributeMaxDynamicSharedMemorySize, GEMM_SMEM);

    const int ROWS = kB * kL;                      // 65536 rows of 128

    k_wcvt<<<128, 256, 0, s1>>>(Wg);               // W -> tf32 on side stream
    k_embed_ln<<<ROWS / 8, 256>>>(ids, (const float4*)emb, ln_w, ln_b);
    cudaEventRecord(evXn[0], 0);

    for (int l = 0; l < 2; l++) {
        const float* Rl = Rg + (size_t)l * 4 * 4 * 32 * 32;
        const float* bl = bg + l * 512;

        cudaStreamWaitEvent(s1, evXn[l], 0);
        for (int c = 0; c < kNC; c++) {
            k_gemm_c<<<dim3(4, 32), 128, GEMM_SMEM, s1>>>(l, c, bl);
            cudaEventRecord(evG[l][c], s1);
        }
        for (int c = 0; c < kNC; c++) {
            cudaStreamWaitEvent(0, evG[l][c], 0);
            if (c == 0) k_scan_c<true ><<<128, 128>>>(Rl, c);
            else        k_scan_c<false><<<128, 128>>>(Rl, c);
        }
        if (l == 0) {
            k_gn<true ><<<ROWS / 8, 256>>>(gn_w, ln_w + 128, ln_b + 128);
            cudaEventRecord(evXn[1], 0);
        } else {
            k_gn<false><<<ROWS / 8, 256>>>(gn_w + 128, nullptr, nullptr);
        }
    }

    k_head<<<512, 128>>>(w1, b1, w2, b2, out);
}

// round 10
// speedup vs baseline: 1.1417x; 1.1417x over previous
#include <cuda_runtime.h>

// Problem constants
constexpr int kB = 512;   // batch
constexpr int kL = 128;   // seq len
constexpr int kD = 128;   // model dim
// H = 4 heads of 32
constexpr int kTC = 32;   // timesteps per chunk
constexpr int kNC = kL / kTC;  // 4 chunks

// Scratch (device globals: allocation-free rule)
__device__ float    g_x [kB * kL * kD];               // residual stream, [b][t][d]
__device__ unsigned g_xn[kB * kL * kD];               // LN output, tf32 bit patterns
__device__ float    g_h [kB * kL * kD];               // raw scan output h
__device__ float    g_pre[(size_t)kL * kB * 4 * kD];  // gate preacts, [t][b][g][d]
__device__ unsigned g_Wt[2 * 4 * kD * kD];            // W rounded to tf32
__device__ float    g_state[4][kB][kD];               // scan state h,c,n,m between chunks

typedef unsigned long long ull;

__device__ __forceinline__ ull pack2(float lo, float hi) {
    ull r; asm("mov.b64 %0,{%1,%2};" : "=l"(r) : "f"(lo), "f"(hi)); return r;
}
__device__ __forceinline__ void unpack2(ull v, float& lo, float& hi) {
    asm("mov.b64 {%0,%1},%2;" : "=f"(lo), "=f"(hi) : "l"(v));
}
__device__ __forceinline__ ull ffma2(ull a, ull b, ull c) {
    ull d; asm("fma.rn.f32x2 %0,%1,%2,%3;" : "=l"(d) : "l"(a), "l"(b), "l"(c)); return d;
}
__device__ __forceinline__ float tanh_fast(float x) {
    float y; asm("tanh.approx.f32 %0,%1;" : "=f"(y) : "f"(x)); return y;
}
__device__ __forceinline__ unsigned to_tf32(float f) {
    unsigned u; asm("cvt.rna.tf32.f32 %0, %1;" : "=r"(u) : "f"(f)); return u;
}

__device__ __forceinline__ void cp_async16(unsigned smem, const void* gptr) {
    asm volatile("cp.async.cg.shared.global [%0], [%1], 16;" :: "r"(smem), "l"(gptr));
}
__device__ __forceinline__ void cp_commit() {
    asm volatile("cp.async.commit_group;");
}
template<int N>
__device__ __forceinline__ void cp_wait() {
    asm volatile("cp.async.wait_group %0;" :: "n"(N));
}

// ---------------------------------------------------------------------------
// W -> tf32 pre-round (both layers, once per launch)
// ---------------------------------------------------------------------------
__global__ void k_wcvt(const float* __restrict__ Wg) {
    int i = blockIdx.x * 256 + threadIdx.x;
    #pragma unroll
    for (int j = 0; j < 4; j++) {
        int e = i * 4 + j;
        g_Wt[e] = to_tf32(__ldg(&Wg[e]));
    }
}

// ---------------------------------------------------------------------------
// Fused embedding gather + LayerNorm(layer0). One warp per row of 128.
// ---------------------------------------------------------------------------
__global__ void k_embed_ln(const int* __restrict__ ids, const float4* __restrict__ emb,
                           const float* __restrict__ w, const float* __restrict__ bb) {
    int t    = blockIdx.x * 256 + threadIdx.x;
    int row  = t >> 5;
    int lane = t & 31;
    int id   = __ldg(&ids[row]);
    float4 v = emb[(size_t)id * 32 + lane];
    ((float4*)g_x)[(size_t)row * 32 + lane] = v;
    float s = v.x + v.y + v.z + v.w;
    float q = v.x*v.x + v.y*v.y + v.z*v.z + v.w*v.w;
    #pragma unroll
    for (int o = 16; o; o >>= 1) {
        s += __shfl_xor_sync(0xffffffffu, s, o);
        q += __shfl_xor_sync(0xffffffffu, q, o);
    }
    float mu  = s * (1.f / 128.f);
    float var = fmaxf(q * (1.f / 128.f) - mu * mu, 0.f);
    float rs  = rsqrtf(var + 1e-5f);
    float4 wv = ((const float4*)w)[lane];
    float4 bv = ((const float4*)bb)[lane];
    uint4 o4;
    o4.x = to_tf32((v.x - mu) * rs * wv.x + bv.x);
    o4.y = to_tf32((v.y - mu) * rs * wv.y + bv.y);
    o4.z = to_tf32((v.z - mu) * rs * wv.z + bv.z);
    o4.w = to_tf32((v.w - mu) * rs * wv.w + bv.w);
    ((uint4*)g_xn)[(size_t)row * 32 + lane] = o4;
}

// ---------------------------------------------------------------------------
// Chunked GroupNorm + residual (+ optional LayerNorm->tf32 for next layer).
// One warp per (b, t) row with t in chunk. 128-thread blocks, ~6K regs/CTA so
// these co-reside with scan CTAs and overlap the NEXT scan chunk.
// ---------------------------------------------------------------------------
template<bool DO_LN>
__global__ void __launch_bounds__(128) k_gn_c(const float* __restrict__ gnw,
                                              const float* __restrict__ lnw,
                                              const float* __restrict__ lnb,
                                              int chunk) {
    const unsigned FULL = 0xffffffffu;
    int idx  = blockIdx.x * 128 + threadIdx.x;
    int r    = idx >> 5;                      // 0 .. kB*kTC-1
    int lane = idx & 31;
    int b    = r >> 5;                        // r / kTC
    int t    = chunk * kTC + (r & 31);
    size_t row = (size_t)b * kL + t;

    float4 hv = ((const float4*)g_h)[row * 32 + lane];
    float4 xv = ((const float4*)g_x)[row * 32 + lane];
    float s = hv.x + hv.y + hv.z + hv.w;
    float q = hv.x*hv.x + hv.y*hv.y + hv.z*hv.z + hv.w*hv.w;
    #pragma unroll
    for (int o = 1; o < 8; o <<= 1) {         // reduce within 8-lane head group
        s += __shfl_xor_sync(FULL, s, o);
        q += __shfl_xor_sync(FULL, q, o);
    }
    float mu  = s * (1.f / 32.f);
    float var = fmaxf(q * (1.f / 32.f) - mu * mu, 0.f);
    float rs  = rsqrtf(var + 1e-5f);
    float4 gw = ((const float4*)gnw)[lane];
    float4 xp;
    xp.x = xv.x + (hv.x - mu) * rs * gw.x;
    xp.y = xv.y + (hv.y - mu) * rs * gw.y;
    xp.z = xv.z + (hv.z - mu) * rs * gw.z;
    xp.w = xv.w + (hv.w - mu) * rs * gw.w;
    ((float4*)g_x)[row * 32 + lane] = xp;

    if (DO_LN) {
        float s2 = xp.x + xp.y + xp.z + xp.w;
        float q2 = xp.x*xp.x + xp.y*xp.y + xp.z*xp.z + xp.w*xp.w;
        #pragma unroll
        for (int o = 16; o; o >>= 1) {
            s2 += __shfl_xor_sync(FULL, s2, o);
            q2 += __shfl_xor_sync(FULL, q2, o);
        }
        float mu2  = s2 * (1.f / 128.f);
        float var2 = fmaxf(q2 * (1.f / 128.f) - mu2 * mu2, 0.f);
        float rs2  = rsqrtf(var2 + 1e-5f);
        float4 wv = ((const float4*)lnw)[lane];
        float4 bv = ((const float4*)lnb)[lane];
        uint4 o4;
        o4.x = to_tf32((xp.x - mu2) * rs2 * wv.x + bv.x);
        o4.y = to_tf32((xp.y - mu2) * rs2 * wv.y + bv.y);
        o4.z = to_tf32((xp.z - mu2) * rs2 * wv.z + bv.z);
        o4.w = to_tf32((xp.w - mu2) * rs2 * wv.w + bv.w);
        ((uint4*)g_xn)[row * 32 + lane] = o4;
    }
}

// ---------------------------------------------------------------------------
// tf32 GEMM (round-6 best): inputs pre-rounded tf32. grid (4, 128):
// bn = gate (fastest, A dedups in L2), bmg = group of 4 row tiles.
// B resident; A double-buffered via cp.async. 256 threads, 2x4 warps.
// ---------------------------------------------------------------------------
__global__ void __launch_bounds__(256) k_gemm(int layer,
                                              const float* __restrict__ bias) {
    constexpr int STR = 132;                 // padded smem stride (words)
    extern __shared__ unsigned sh[];
    unsigned* Bs = sh;                       // [128][132]
    unsigned* As0 = sh + 128 * STR;          // double buffer
    unsigned* As1 = As0 + 128 * STR;

    int tid = threadIdx.x;
    int bn  = blockIdx.x;                    // gate
    int bmg = blockIdx.y;                    // group of 4 row tiles

    const unsigned* Wg = g_Wt + (size_t)(layer * 4 + bn) * 128 * 128;
    unsigned As0_u = (unsigned)__cvta_generic_to_shared(As0);
    unsigned As1_u = (unsigned)__cvta_generic_to_shared(As1);
    unsigned Bs_u  = (unsigned)__cvta_generic_to_shared(Bs);

    #pragma unroll
    for (int i = 0; i < 16; i++) {
        int e = i * 256 + tid, rr = e >> 5, c4 = e & 31;
        cp_async16(Bs_u + (rr * STR + c4 * 4) * 4, Wg + rr * 128 + c4 * 4);
    }
    {
        const unsigned* Ag = g_xn + (size_t)(bmg * 4 + 0) * 128 * 128;
        #pragma unroll
        for (int i = 0; i < 16; i++) {
            int e = i * 256 + tid, rr = e >> 5, c4 = e & 31;
            cp_async16(As0_u + (rr * STR + c4 * 4) * 4, Ag + rr * 128 + c4 * 4);
        }
    }
    cp_commit();
    {
        const unsigned* Ag = g_xn + (size_t)(bmg * 4 + 1) * 128 * 128;
        #pragma unroll
        for (int i = 0; i < 16; i++) {
            int e = i * 256 + tid, rr = e >> 5, c4 = e & 31;
            cp_async16(As1_u + (rr * STR + c4 * 4) * 4, Ag + rr * 128 + c4 * 4);
        }
    }
    cp_commit();

    int warp = tid >> 5, lane = tid & 31;
    int wm = warp >> 2, wn = warp & 3;
    int gid = lane >> 2, tg = lane & 3;

    float bz[4][2];
    #pragma unroll
    for (int j = 0; j < 4; j++) {
        int col = bn * 128 + wn * 32 + j * 8 + tg * 2;
        bz[j][0] = __ldg(&bias[col]);
        bz[j][1] = __ldg(&bias[col + 1]);
    }

    #pragma unroll
    for (int it = 0; it < 4; it++) {
        unsigned* As = (it & 1) ? As1 : As0;
        if (it < 3) cp_wait<1>(); else cp_wait<0>();
        __syncthreads();

        float acc[4][4][4];
        #pragma unroll
        for (int i = 0; i < 4; i++)
            #pragma unroll
            for (int j = 0; j < 4; j++)
                #pragma unroll
                for (int c = 0; c < 4; c++) acc[i][j][c] = 0.f;

        #pragma unroll
        for (int ks = 0; ks < 16; ks++) {
            int k0 = ks * 8 + tg;
            unsigned a[4][4], bf[4][2];
            #pragma unroll
            for (int i = 0; i < 4; i++) {
                int r0 = wm * 64 + i * 16 + gid;
                a[i][0] = As[r0 * STR + k0];
                a[i][1] = As[(r0 + 8) * STR + k0];
                a[i][2] = As[r0 * STR + k0 + 4];
                a[i][3] = As[(r0 + 8) * STR + k0 + 4];
            }
            #pragma unroll
            for (int j = 0; j < 4; j++) {
                int n0 = wn * 32 + j * 8 + gid;
                bf[j][0] = Bs[n0 * STR + k0];
                bf[j][1] = Bs[n0 * STR + k0 + 4];
            }
            #pragma unroll
            for (int i = 0; i < 4; i++)
                #pragma unroll
                for (int j = 0; j < 4; j++)
                    asm volatile(
                        "mma.sync.aligned.m16n8k8.row.col.f32.tf32.tf32.f32 "
                        "{%0,%1,%2,%3}, {%4,%5,%6,%7}, {%8,%9}, {%0,%1,%2,%3};"
                        : "+f"(acc[i][j][0]), "+f"(acc[i][j][1]),
                          "+f"(acc[i][j][2]), "+f"(acc[i][j][3])
                        : "r"(a[i][0]), "r"(a[i][1]), "r"(a[i][2]), "r"(a[i][3]),
                          "r"(bf[j][0]), "r"(bf[j][1]));
        }
        __syncthreads();

        if (it + 2 < 4) {
            unsigned dst = (it & 1) ? As1_u : As0_u;
            const unsigned* Ag = g_xn + (size_t)(bmg * 4 + it + 2) * 128 * 128;
            #pragma unroll
            for (int i = 0; i < 16; i++) {
                int e = i * 256 + tid, rr = e >> 5, c4 = e & 31;
                cp_async16(dst + (rr * STR + c4 * 4) * 4, Ag + rr * 128 + c4 * 4);
            }
            cp_commit();
        }

        int bm = bmg * 4 + it;
        #pragma unroll
        for (int i = 0; i < 4; i++) {
            int r0 = bm * 128 + wm * 64 + i * 16 + gid;
            int ra = r0, rb = r0 + 8;
            float* outa = g_pre + ((size_t)(ra & 127) * 512 + (ra >> 7)) * 512;
            float* outb = g_pre + ((size_t)(rb & 127) * 512 + (rb >> 7)) * 512;
            #pragma unroll
            for (int j = 0; j < 4; j++) {
                int col = bn * 128 + wn * 32 + j * 8 + tg * 2;
                *(float2*)&outa[col] = make_float2(acc[i][j][0] + bz[j][0], acc[i][j][1] + bz[j][1]);
                *(float2*)&outb[col] = make_float2(acc[i][j][2] + bz[j][0], acc[i][j][3] + bz[j][1]);
            }
        }
    }
}

// ---------------------------------------------------------------------------
// sLSTM gate math: 5 MUFU (3 ex2 + tanh + rcp)
// ---------------------------------------------------------------------------
__device__ __forceinline__ void gate_step(float ai, float af, float az, float ao,
                                          float& h, float& c, float& n, float& m) {
    float fm = af + m;
    float mn = fmaxf(fm, ai);
    float iv = __expf(ai - mn);
    float fv = __expf(fm - mn);
    float th = tanh_fast(az);
    c = fmaf(fv, c, iv * th);
    n = fmaf(fv, n, iv);
    float eo = __expf(-ao);                   // h = sigmoid(ao) * c / n
    float denom = fmaf(n, eo, n);             //   = c / (n * (1 + e^-ao))
    h = __fdividef(c, denom);
    m = mn;
}

// ---------------------------------------------------------------------------
// Recurrent sLSTM scan, one 32-step chunk (round-3 body; best known).
// 256 threads, 2 batches/thread, warp = head, smem h broadcast, no barriers.
// State carried in g_state between chunk launches.
// ---------------------------------------------------------------------------
template<bool FIRST>
__global__ void __launch_bounds__(256, 1) k_scan_c(const float* __restrict__ R, int chunk) {
    __shared__ float shA[2][2][4][32];        // [slot][grp][head][d]
    __shared__ float shB[2][2][4][32];

    int o    = threadIdx.x & 127;            // output dim
    int grp  = threadIdx.x >> 7;             // batch pair within CTA
    int hh   = (threadIdx.x >> 5) & 3;       // head
    int lane = threadIdx.x & 31;

    int b0 = blockIdx.x * 4 + grp * 2;       // batch A; batch B = b0+1

    ull Rr2[64];
    #pragma unroll
    for (int g = 0; g < 4; g++)
        #pragma unroll
        for (int dp = 0; dp < 16; dp++) {
            float r0 = __ldg(&R[((g * 4 + hh) * 32 + 2 * dp)     * 32 + lane]);
            float r1 = __ldg(&R[((g * 4 + hh) * 32 + 2 * dp + 1) * 32 + lane]);
            Rr2[g * 16 + dp] = pack2(r0, r1);
        }

    float hA, cA, nA, mA, hB, cB, nB, mB;
    if (FIRST) {
        hA = cA = nA = mA = 0.f;
        hB = cB = nB = mB = 0.f;
    } else {
        hA = g_state[0][b0][o];   cA = g_state[1][b0][o];
        nA = g_state[2][b0][o];   mA = g_state[3][b0][o];
        hB = g_state[0][b0+1][o]; cB = g_state[1][b0+1][o];
        nB = g_state[2][b0+1][o]; mB = g_state[3][b0+1][o];
    }

    const float* pA = g_pre + (size_t)(chunk * kTC) * (kB * 512) + (size_t)b0 * 512 + o;
    const float* pB = pA + 512;
    float* hoA = g_h + (size_t)b0 * kL * kD + (size_t)(chunk * kTC) * kD + o;
    float* hoB = hoA + (size_t)kL * kD;

    float a0 = pA[0], a1 = pA[128], a2 = pA[256], a3 = pA[384];
    float q0 = pB[0], q1 = pB[128], q2 = pB[256], q3 = pB[384];

    for (int t = 0; t < kTC; t++) {
        int s = t & 1;
        shA[s][grp][hh][lane] = hA;
        shB[s][grp][hh][lane] = hB;
        __syncwarp();

        // accumulators carry the preactivation in the low half
        ull aiA = pack2(a0, 0.f), afA = pack2(a1, 0.f);
        ull azA = pack2(a2, 0.f), aoA = pack2(a3, 0.f);
        ull aiB = pack2(q0, 0.f), afB = pack2(q1, 0.f);
        ull azB = pack2(q2, 0.f), aoB = pack2(q3, 0.f);

        if (t + 1 < kTC) {
            const float* nA_ = pA + (size_t)(t + 1) * (kB * 512);
            const float* nB_ = pB + (size_t)(t + 1) * (kB * 512);
            a0 = nA_[0]; a1 = nA_[128]; a2 = nA_[256]; a3 = nA_[384];
            q0 = nB_[0]; q1 = nB_[128]; q2 = nB_[256]; q3 = nB_[384];
        }

        const float4* h4A = (const float4*)shA[s][grp][hh];
        const float4* h4B = (const float4*)shB[s][grp][hh];
        #pragma unroll
        for (int j = 0; j < 8; j++) {
            float4 va = h4A[j];
            float4 vb = h4B[j];
            ull a01 = pack2(va.x, va.y), a23 = pack2(va.z, va.w);
            ull b01 = pack2(vb.x, vb.y), b23 = pack2(vb.z, vb.w);
            int dp = 2 * j;
            aiA = ffma2(a01, Rr2[dp],      aiA); aiA = ffma2(a23, Rr2[dp + 1],      aiA);
            afA = ffma2(a01, Rr2[16 + dp], afA); afA = ffma2(a23, Rr2[16 + dp + 1], afA);
            azA = ffma2(a01, Rr2[32 + dp], azA); azA = ffma2(a23, Rr2[32 + dp + 1], azA);
            aoA = ffma2(a01, Rr2[48 + dp], aoA); aoA = ffma2(a23, Rr2[48 + dp + 1], aoA);
            aiB = ffma2(b01, Rr2[dp],      aiB); aiB = ffma2(b23, Rr2[dp + 1],      aiB);
            afB = ffma2(b01, Rr2[16 + dp], afB); afB = ffma2(b23, Rr2[16 + dp + 1], afB);
            azB = ffma2(b01, Rr2[32 + dp], azB); azB = ffma2(b23, Rr2[32 + dp + 1], azB);
            aoB = ffma2(b01, Rr2[48 + dp], aoB); aoB = ffma2(b23, Rr2[48 + dp + 1], aoB);
        }

        float lo, hi;
        unpack2(aiA, lo, hi); float gAi = lo + hi;
        unpack2(afA, lo, hi); float gAf = lo + hi;
        unpack2(azA, lo, hi); float gAz = lo + hi;
        unpack2(aoA, lo, hi); float gAo = lo + hi;
        unpack2(aiB, lo, hi); float gBi = lo + hi;
        unpack2(afB, lo, hi); float gBf = lo + hi;
        unpack2(azB, lo, hi); float gBz = lo + hi;
        unpack2(aoB, lo, hi); float gBo = lo + hi;

        gate_step(gAi, gAf, gAz, gAo, hA, cA, nA, mA);
        gate_step(gBi, gBf, gBz, gBo, hB, cB, nB, mB);

        hoA[(size_t)t * kD] = hA;
        hoB[(size_t)t * kD] = hB;
    }

    g_state[0][b0][o]   = hA; g_state[1][b0][o]   = cA;
    g_state[2][b0][o]   = nA; g_state[3][b0][o]   = mA;
    g_state[0][b0+1][o] = hB; g_state[1][b0+1][o] = cB;
    g_state[2][b0+1][o] = nB; g_state[3][b0+1][o] = mB;
}

// ---------------------------------------------------------------------------
// Head: mean over time, then 128->64 ReLU MLP, then 64->2
// ---------------------------------------------------------------------------
__global__ void k_head(const float* __restrict__ w1, const float* __restrict__ b1,
                       const float* __restrict__ w2, const float* __restrict__ b2,
                       float* __restrict__ out) {
    __shared__ float pooled[128];
    __shared__ float hid[64];
    int b = blockIdx.x, o = threadIdx.x;
    const float* xb = g_x + (size_t)b * kL * kD + o;
    float s = 0.f;
    #pragma unroll 8
    for (int t = 0; t < kL; t++) s += xb[(size_t)t * kD];
    pooled[o] = s * (1.f / 128.f);
    __syncthreads();
    if (o < 64) {
        float a = __ldg(&b1[o]);
        const float* wr = w1 + o * 128;
        #pragma unroll
        for (int d = 0; d < 128; d++) a = fmaf(pooled[d], __ldg(&wr[d]), a);
        hid[o] = fmaxf(a, 0.f);
    }
    __syncthreads();
    if (o < 2) {
        float a = __ldg(&b2[o]);
        const float* wr = w2 + o * 64;
        #pragma unroll
        for (int j = 0; j < 64; j++) a = fmaf(hid[j], __ldg(&wr[j]), a);
        out[b * 2 + o] = a;
    }
}

// ---------------------------------------------------------------------------
extern "C" void kernel_launch(void* const* d_in, const int* in_sizes, int n_in,
                              void* d_out, int out_size) {
    const int*   ids  = (const int*)  d_in[0];
    const float* emb  = (const float*)d_in[1];
    const float* ln_w = (const float*)d_in[2];
    const float* ln_b = (const float*)d_in[3];
    const float* Wg   = (const float*)d_in[4];
    const float* Rg   = (const float*)d_in[5];
    const float* bg   = (const float*)d_in[6];
    const float* gn_w = (const float*)d_in[7];
    const float* w1   = (const float*)d_in[8];
    const float* b1   = (const float*)d_in[9];
    const float* w2   = (const float*)d_in[10];
    const float* b2   = (const float*)d_in[11];
    float* out = (float*)d_out;

    // one-time stream/event creation (host resources only; no device memory)
    static cudaStream_t s1 = nullptr;
    static cudaEvent_t evS[2][kNC];           // scan chunk done (default stream)
    static cudaEvent_t evGN[2][kNC];          // gn chunk done (s1)
    if (!s1) {
        cudaStreamCreateWithFlags(&s1, cudaStreamNonBlocking);
        for (int l = 0; l < 2; l++)
            for (int c = 0; c < kNC; c++) {
                cudaEventCreateWithFlags(&evS[l][c], cudaEventDisableTiming);
                cudaEventCreateWithFlags(&evGN[l][c], cudaEventDisableTiming);
            }
    }

    constexpr int GEMM_SMEM = 3 * 128 * 132 * 4;   // 202752 B
    cudaFuncSetAttribute(k_gemm, cudaFuncAttributeMaxDynamicSharedMemorySize, GEMM_SMEM);

    const int ROWS = kB * kL;                      // 65536 rows of 128
    const int GN_BLOCKS = kB * kTC * 32 / 128;     // 4096 blocks per chunk

    // Everything forks FROM the captured stream (0); all s1 activity begins
    // with a wait on an event recorded inside the capture.
    k_wcvt<<<128, 256>>>(Wg);
    k_embed_ln<<<ROWS / 8, 256>>>(ids, (const float4*)emb, ln_w, ln_b);

    for (int l = 0; l < 2; l++) {
        const float* Rl = Rg + (size_t)l * 4 * 4 * 32 * 32;
        const float* bl = bg + l * 512;

        if (l == 1) cudaStreamWaitEvent(0, evGN[0][kNC - 1], 0);  // needs all g_xn
        k_gemm<<<dim3(4, 128), 256, GEMM_SMEM>>>(l, bl);

        for (int c = 0; c < kNC; c++) {
            if (c == 0) k_scan_c<true ><<<128, 256>>>(Rl, c);
            else        k_scan_c<false><<<128, 256>>>(Rl, c);
            cudaEventRecord(evS[l][c], 0);
        }
        // gn chunks on side stream: chunk c starts when scan chunk c is done,
        // and (low-reg, no-smem) co-resides with scan chunk c+1.
        for (int c = 0; c < kNC; c++) {
            cudaStreamWaitEvent(s1, evS[l][c], 0);
            if (l == 0)
                k_gn_c<true ><<<GN_BLOCKS, 128, 0, s1>>>(gn_w, ln_w + 128, ln_b + 128, c);
            else
                k_gn_c<false><<<GN_BLOCKS, 128, 0, s1>>>(gn_w + 128, nullptr, nullptr, c);
            cudaEventRecord(evGN[l][c], s1);
        }
    }

    cudaStreamWaitEvent(0, evGN[1][kNC - 1], 0);
    k_head<<<512, 128>>>(w1, b1, w2, b2, out);
}

// round 11
// speedup vs baseline: 1.2549x; 1.0992x over previous
#include <cuda_runtime.h>

// Problem constants
constexpr int kB = 512;   // batch
constexpr int kL = 128;   // seq len
constexpr int kD = 128;   // model dim
// H = 4 heads of 32

// Scratch (device globals: allocation-free rule)
__device__ float    g_x [kB * kL * kD];               // residual stream, [b][t][d]
__device__ unsigned g_xn[kB * kL * kD];               // LN output, tf32 bit patterns
__device__ float    g_h [kB * kL * kD];               // raw scan output h
__device__ float    g_pre[(size_t)kL * kB * 4 * kD];  // gate preacts, [t][b][g][d]
__device__ unsigned g_Wt[2 * 4 * kD * kD];            // W rounded to tf32

typedef unsigned long long ull;

__device__ __forceinline__ ull pack2(float lo, float hi) {
    ull r; asm("mov.b64 %0,{%1,%2};" : "=l"(r) : "f"(lo), "f"(hi)); return r;
}
__device__ __forceinline__ void unpack2(ull v, float& lo, float& hi) {
    asm("mov.b64 {%0,%1},%2;" : "=f"(lo), "=f"(hi) : "l"(v));
}
__device__ __forceinline__ ull ffma2(ull a, ull b, ull c) {
    ull d; asm("fma.rn.f32x2 %0,%1,%2,%3;" : "=l"(d) : "l"(a), "l"(b), "l"(c)); return d;
}
__device__ __forceinline__ float tanh_fast(float x) {
    float y; asm("tanh.approx.f32 %0,%1;" : "=f"(y) : "f"(x)); return y;
}
__device__ __forceinline__ unsigned to_tf32(float f) {
    unsigned u; asm("cvt.rna.tf32.f32 %0, %1;" : "=r"(u) : "f"(f)); return u;
}

__device__ __forceinline__ void cp_async16(unsigned smem, const void* gptr) {
    asm volatile("cp.async.cg.shared.global [%0], [%1], 16;" :: "r"(smem), "l"(gptr));
}
__device__ __forceinline__ void cp_commit() {
    asm volatile("cp.async.commit_group;");
}
template<int N>
__device__ __forceinline__ void cp_wait() {
    asm volatile("cp.async.wait_group %0;" :: "n"(N));
}

// ---------------------------------------------------------------------------
// W -> tf32 pre-round (both layers, once per launch)
// ---------------------------------------------------------------------------
__global__ void k_wcvt(const float* __restrict__ Wg) {
    int i = blockIdx.x * 256 + threadIdx.x;
    #pragma unroll
    for (int j = 0; j < 4; j++) {
        int e = i * 4 + j;
        g_Wt[e] = to_tf32(__ldg(&Wg[e]));
    }
}

// ---------------------------------------------------------------------------
// Fused embedding gather + LayerNorm(layer0). One warp per row of 128.
// ---------------------------------------------------------------------------
__global__ void k_embed_ln(const int* __restrict__ ids, const float4* __restrict__ emb,
                           const float* __restrict__ w, const float* __restrict__ bb) {
    int t    = blockIdx.x * 256 + threadIdx.x;
    int row  = t >> 5;
    int lane = t & 31;
    int id   = __ldg(&ids[row]);
    float4 v = emb[(size_t)id * 32 + lane];
    ((float4*)g_x)[(size_t)row * 32 + lane] = v;
    float s = v.x + v.y + v.z + v.w;
    float q = v.x*v.x + v.y*v.y + v.z*v.z + v.w*v.w;
    #pragma unroll
    for (int o = 16; o; o >>= 1) {
        s += __shfl_xor_sync(0xffffffffu, s, o);
        q += __shfl_xor_sync(0xffffffffu, q, o);
    }
    float mu  = s * (1.f / 128.f);
    float var = fmaxf(q * (1.f / 128.f) - mu * mu, 0.f);
    float rs  = rsqrtf(var + 1e-5f);
    float4 wv = ((const float4*)w)[lane];
    float4 bv = ((const float4*)bb)[lane];
    uint4 o4;
    o4.x = to_tf32((v.x - mu) * rs * wv.x + bv.x);
    o4.y = to_tf32((v.y - mu) * rs * wv.y + bv.y);
    o4.z = to_tf32((v.z - mu) * rs * wv.z + bv.z);
    o4.w = to_tf32((v.w - mu) * rs * wv.w + bv.w);
    ((uint4*)g_xn)[(size_t)row * 32 + lane] = o4;
}

// ---------------------------------------------------------------------------
// Fused GroupNorm + residual (+ optional LayerNorm->tf32 for next layer).
// ---------------------------------------------------------------------------
template<bool DO_LN>
__global__ void k_gn(const float* __restrict__ gnw,
                     const float* __restrict__ lnw, const float* __restrict__ lnb) {
    const unsigned FULL = 0xffffffffu;
    int t    = blockIdx.x * 256 + threadIdx.x;
    int row  = t >> 5;
    int lane = t & 31;
    float4 hv = ((const float4*)g_h)[(size_t)row * 32 + lane];
    float4 xv = ((const float4*)g_x)[(size_t)row * 32 + lane];
    float s = hv.x + hv.y + hv.z + hv.w;
    float q = hv.x*hv.x + hv.y*hv.y + hv.z*hv.z + hv.w*hv.w;
    #pragma unroll
    for (int o = 1; o < 8; o <<= 1) {
        s += __shfl_xor_sync(FULL, s, o);
        q += __shfl_xor_sync(FULL, q, o);
    }
    float mu  = s * (1.f / 32.f);
    float var = fmaxf(q * (1.f / 32.f) - mu * mu, 0.f);
    float rs  = rsqrtf(var + 1e-5f);
    float4 gw = ((const float4*)gnw)[lane];
    float4 xp;
    xp.x = xv.x + (hv.x - mu) * rs * gw.x;
    xp.y = xv.y + (hv.y - mu) * rs * gw.y;
    xp.z = xv.z + (hv.z - mu) * rs * gw.z;
    xp.w = xv.w + (hv.w - mu) * rs * gw.w;
    ((float4*)g_x)[(size_t)row * 32 + lane] = xp;

    if (DO_LN) {
        float s2 = xp.x + xp.y + xp.z + xp.w;
        float q2 = xp.x*xp.x + xp.y*xp.y + xp.z*xp.z + xp.w*xp.w;
        #pragma unroll
        for (int o = 16; o; o >>= 1) {
            s2 += __shfl_xor_sync(FULL, s2, o);
            q2 += __shfl_xor_sync(FULL, q2, o);
        }
        float mu2  = s2 * (1.f / 128.f);
        float var2 = fmaxf(q2 * (1.f / 128.f) - mu2 * mu2, 0.f);
        float rs2  = rsqrtf(var2 + 1e-5f);
        float4 wv = ((const float4*)lnw)[lane];
        float4 bv = ((const float4*)lnb)[lane];
        uint4 o4;
        o4.x = to_tf32((xp.x - mu2) * rs2 * wv.x + bv.x);
        o4.y = to_tf32((xp.y - mu2) * rs2 * wv.y + bv.y);
        o4.z = to_tf32((xp.z - mu2) * rs2 * wv.z + bv.z);
        o4.w = to_tf32((xp.w - mu2) * rs2 * wv.w + bv.w);
        ((uint4*)g_xn)[(size_t)row * 32 + lane] = o4;
    }
}

// ---------------------------------------------------------------------------
// tf32 GEMM v3: K tiled into 4 chunks of 32, double-buffered (74 KB smem)
// with __launch_bounds__(256,2) -> 2 CTAs/SM, 4 warps/SMSP (latency hidden).
// Each CTA: one 128x128 output tile (bm = batch), full K via chunk loop.
// grid (4, 512): bn = gate (fastest -> A chunks dedup in L2 across the 4
// gates), bm = row tile. B chunks hit L2 (256 KB/layer across 512 CTAs).
// ---------------------------------------------------------------------------
constexpr int GSTR = 36;                      // padded chunk stride (words)
constexpr int GEMM_SMEM = 4 * 128 * GSTR * 4; // A[2]+B[2] = 73728 B

__global__ void __launch_bounds__(256, 2) k_gemm(int layer,
                                                 const float* __restrict__ bias) {
    extern __shared__ unsigned sh[];
    unsigned* As0 = sh;
    unsigned* As1 = sh + 128 * GSTR;
    unsigned* Bs0 = sh + 2 * 128 * GSTR;
    unsigned* Bs1 = sh + 3 * 128 * GSTR;

    int tid = threadIdx.x;
    int bn  = blockIdx.x;                     // gate
    int bm  = blockIdx.y;                     // row tile == batch

    const unsigned* Ag = g_xn + (size_t)bm * 128 * 128;
    const unsigned* Wg = g_Wt + (size_t)(layer * 4 + bn) * 128 * 128;
    unsigned As_u[2] = { (unsigned)__cvta_generic_to_shared(As0),
                         (unsigned)__cvta_generic_to_shared(As1) };
    unsigned Bs_u[2] = { (unsigned)__cvta_generic_to_shared(Bs0),
                         (unsigned)__cvta_generic_to_shared(Bs1) };

    // issue one K-chunk (A + B) into buffer buf
    auto issue = [&](int buf, int kc) {
        #pragma unroll
        for (int i = 0; i < 4; i++) {
            int e = i * 256 + tid, rr = e >> 3, cc = e & 7;
            cp_async16(As_u[buf] + (rr * GSTR + cc * 4) * 4,
                       Ag + rr * 128 + kc * 32 + cc * 4);
            cp_async16(Bs_u[buf] + (rr * GSTR + cc * 4) * 4,
                       Wg + rr * 128 + kc * 32 + cc * 4);
        }
        cp_commit();
    };
    issue(0, 0);
    issue(1, 1);

    int warp = tid >> 5, lane = tid & 31;
    int wm = warp >> 2, wn = warp & 3;        // 2x4 warps, 64x32 warp tiles
    int gid = lane >> 2, tg = lane & 3;

    float bz[4][2];
    #pragma unroll
    for (int j = 0; j < 4; j++) {
        int col = bn * 128 + wn * 32 + j * 8 + tg * 2;
        bz[j][0] = __ldg(&bias[col]);
        bz[j][1] = __ldg(&bias[col + 1]);
    }

    float acc[4][4][4];
    #pragma unroll
    for (int i = 0; i < 4; i++)
        #pragma unroll
        for (int j = 0; j < 4; j++)
            #pragma unroll
            for (int c = 0; c < 4; c++) acc[i][j][c] = 0.f;

    #pragma unroll
    for (int kc = 0; kc < 4; kc++) {
        unsigned* As = (kc & 1) ? As1 : As0;
        unsigned* Bs = (kc & 1) ? Bs1 : Bs0;
        if (kc < 3) cp_wait<1>(); else cp_wait<0>();
        __syncthreads();

        #pragma unroll
        for (int ks = 0; ks < 4; ks++) {
            int k0 = ks * 8 + tg;
            unsigned a[4][4], bf[4][2];
            #pragma unroll
            for (int i = 0; i < 4; i++) {
                int r0 = wm * 64 + i * 16 + gid;
                a[i][0] = As[r0 * GSTR + k0];
                a[i][1] = As[(r0 + 8) * GSTR + k0];
                a[i][2] = As[r0 * GSTR + k0 + 4];
                a[i][3] = As[(r0 + 8) * GSTR + k0 + 4];
            }
            #pragma unroll
            for (int j = 0; j < 4; j++) {
                int n0 = wn * 32 + j * 8 + gid;
                bf[j][0] = Bs[n0 * GSTR + k0];
                bf[j][1] = Bs[n0 * GSTR + k0 + 4];
            }
            #pragma unroll
            for (int i = 0; i < 4; i++)
                #pragma unroll
                for (int j = 0; j < 4; j++)
                    asm volatile(
                        "mma.sync.aligned.m16n8k8.row.col.f32.tf32.tf32.f32 "
                        "{%0,%1,%2,%3}, {%4,%5,%6,%7}, {%8,%9}, {%0,%1,%2,%3};"
                        : "+f"(acc[i][j][0]), "+f"(acc[i][j][1]),
                          "+f"(acc[i][j][2]), "+f"(acc[i][j][3])
                        : "r"(a[i][0]), "r"(a[i][1]), "r"(a[i][2]), "r"(a[i][3]),
                          "r"(bf[j][0]), "r"(bf[j][1]));
        }
        __syncthreads();                       // buffer free before refill

        if (kc + 2 < 4) issue(kc & 1, kc + 2);
    }

    // epilogue: local row l (= timestep), batch = bm
    // pre[(l*512 + bm)*512 + col]
    #pragma unroll
    for (int i = 0; i < 4; i++) {
        int la = wm * 64 + i * 16 + gid;
        int lb = la + 8;
        float* outa = g_pre + ((size_t)la * 512 + bm) * 512;
        float* outb = g_pre + ((size_t)lb * 512 + bm) * 512;
        #pragma unroll
        for (int j = 0; j < 4; j++) {
            int col = bn * 128 + wn * 32 + j * 8 + tg * 2;
            *(float2*)&outa[col] = make_float2(acc[i][j][0] + bz[j][0], acc[i][j][1] + bz[j][1]);
            *(float2*)&outb[col] = make_float2(acc[i][j][2] + bz[j][0], acc[i][j][3] + bz[j][1]);
        }
    }
}

// ---------------------------------------------------------------------------
// sLSTM gate math: 5 MUFU (3 ex2 + tanh + rcp)
// ---------------------------------------------------------------------------
__device__ __forceinline__ void gate_step(float ai, float af, float az, float ao,
                                          float& h, float& c, float& n, float& m) {
    float fm = af + m;
    float mn = fmaxf(fm, ai);
    float iv = __expf(ai - mn);
    float fv = __expf(fm - mn);
    float th = tanh_fast(az);
    c = fmaf(fv, c, iv * th);
    n = fmaf(fv, n, iv);
    float eo = __expf(-ao);                   // h = sigmoid(ao) * c / n
    float denom = fmaf(n, eo, n);             //   = c / (n * (1 + e^-ao))
    h = __fdividef(c, denom);
    m = mn;
}

// ---------------------------------------------------------------------------
// Recurrent sLSTM scan (round-3 body; best measured: 79.3 us/layer).
// Grid 128 x 256, 4 batches/CTA, thread = (batch-pair, o), warp = head.
// h broadcast through SMEM, no barriers, single accumulator chain per gate
// seeded with the preactivation in the low half.
// ---------------------------------------------------------------------------
__global__ void __launch_bounds__(256, 1) k_scan(const float* __restrict__ R) {
    __shared__ float shA[2][2][4][32];        // [slot][grp][head][d]
    __shared__ float shB[2][2][4][32];

    int o    = threadIdx.x & 127;            // output dim
    int grp  = threadIdx.x >> 7;             // batch pair within CTA
    int hh   = (threadIdx.x >> 5) & 3;       // head
    int lane = threadIdx.x & 31;

    int b0 = blockIdx.x * 4 + grp * 2;       // batch A; batch B = b0+1

    ull Rr2[64];
    #pragma unroll
    for (int g = 0; g < 4; g++)
        #pragma unroll
        for (int dp = 0; dp < 16; dp++) {
            float r0 = __ldg(&R[((g * 4 + hh) * 32 + 2 * dp)     * 32 + lane]);
            float r1 = __ldg(&R[((g * 4 + hh) * 32 + 2 * dp + 1) * 32 + lane]);
            Rr2[g * 16 + dp] = pack2(r0, r1);
        }

    float hA = 0.f, cA = 0.f, nA = 0.f, mA = 0.f;
    float hB = 0.f, cB = 0.f, nB = 0.f, mB = 0.f;

    const float* pA = g_pre + (size_t)b0 * 512 + o;
    const float* pB = pA + 512;
    float* hoA = g_h + (size_t)b0 * kL * kD + o;
    float* hoB = hoA + (size_t)kL * kD;

    float a0 = pA[0], a1 = pA[128], a2 = pA[256], a3 = pA[384];
    float q0 = pB[0], q1 = pB[128], q2 = pB[256], q3 = pB[384];

    for (int t = 0; t < kL; t++) {
        int s = t & 1;
        shA[s][grp][hh][lane] = hA;
        shB[s][grp][hh][lane] = hB;
        __syncwarp();

        // accumulators carry the preactivation in the low half
        ull aiA = pack2(a0, 0.f), afA = pack2(a1, 0.f);
        ull azA = pack2(a2, 0.f), aoA = pack2(a3, 0.f);
        ull aiB = pack2(q0, 0.f), afB = pack2(q1, 0.f);
        ull azB = pack2(q2, 0.f), aoB = pack2(q3, 0.f);

        if (t + 1 < kL) {
            const float* nA_ = pA + (size_t)(t + 1) * (kB * 512);
            const float* nB_ = pB + (size_t)(t + 1) * (kB * 512);
            a0 = nA_[0]; a1 = nA_[128]; a2 = nA_[256]; a3 = nA_[384];
            q0 = nB_[0]; q1 = nB_[128]; q2 = nB_[256]; q3 = nB_[384];
        }

        const float4* h4A = (const float4*)shA[s][grp][hh];
        const float4* h4B = (const float4*)shB[s][grp][hh];
        #pragma unroll
        for (int j = 0; j < 8; j++) {
            float4 va = h4A[j];
            float4 vb = h4B[j];
            ull a01 = pack2(va.x, va.y), a23 = pack2(va.z, va.w);
            ull b01 = pack2(vb.x, vb.y), b23 = pack2(vb.z, vb.w);
            int dp = 2 * j;
            aiA = ffma2(a01, Rr2[dp],      aiA); aiA = ffma2(a23, Rr2[dp + 1],      aiA);
            afA = ffma2(a01, Rr2[16 + dp], afA); afA = ffma2(a23, Rr2[16 + dp + 1], afA);
            azA = ffma2(a01, Rr2[32 + dp], azA); azA = ffma2(a23, Rr2[32 + dp + 1], azA);
            aoA = ffma2(a01, Rr2[48 + dp], aoA); aoA = ffma2(a23, Rr2[48 + dp + 1], aoA);
            aiB = ffma2(b01, Rr2[dp],      aiB); aiB = ffma2(b23, Rr2[dp + 1],      aiB);
            afB = ffma2(b01, Rr2[16 + dp], afB); afB = ffma2(b23, Rr2[16 + dp + 1], afB);
            azB = ffma2(b01, Rr2[32 + dp], azB); azB = ffma2(b23, Rr2[32 + dp + 1], azB);
            aoB = ffma2(b01, Rr2[48 + dp], aoB); aoB = ffma2(b23, Rr2[48 + dp + 1], aoB);
        }

        float lo, hi;
        unpack2(aiA, lo, hi); float gAi = lo + hi;
        unpack2(afA, lo, hi); float gAf = lo + hi;
        unpack2(azA, lo, hi); float gAz = lo + hi;
        unpack2(aoA, lo, hi); float gAo = lo + hi;
        unpack2(aiB, lo, hi); float gBi = lo + hi;
        unpack2(afB, lo, hi); float gBf = lo + hi;
        unpack2(azB, lo, hi); float gBz = lo + hi;
        unpack2(aoB, lo, hi); float gBo = lo + hi;

        gate_step(gAi, gAf, gAz, gAo, hA, cA, nA, mA);
        gate_step(gBi, gBf, gBz, gBo, hB, cB, nB, mB);

        hoA[(size_t)t * kD] = hA;
        hoB[(size_t)t * kD] = hB;
    }
}

// ---------------------------------------------------------------------------
// Head: mean over time, then 128->64 ReLU MLP, then 64->2
// ---------------------------------------------------------------------------
__global__ void k_head(const float* __restrict__ w1, const float* __restrict__ b1,
                       const float* __restrict__ w2, const float* __restrict__ b2,
                       float* __restrict__ out) {
    __shared__ float pooled[128];
    __shared__ float hid[64];
    int b = blockIdx.x, o = threadIdx.x;
    const float* xb = g_x + (size_t)b * kL * kD + o;
    float s = 0.f;
    #pragma unroll 8
    for (int t = 0; t < kL; t++) s += xb[(size_t)t * kD];
    pooled[o] = s * (1.f / 128.f);
    __syncthreads();
    if (o < 64) {
        float a = __ldg(&b1[o]);
        const float* wr = w1 + o * 128;
        #pragma unroll
        for (int d = 0; d < 128; d++) a = fmaf(pooled[d], __ldg(&wr[d]), a);
        hid[o] = fmaxf(a, 0.f);
    }
    __syncthreads();
    if (o < 2) {
        float a = __ldg(&b2[o]);
        const float* wr = w2 + o * 64;
        #pragma unroll
        for (int j = 0; j < 64; j++) a = fmaf(hid[j], __ldg(&wr[j]), a);
        out[b * 2 + o] = a;
    }
}

// ---------------------------------------------------------------------------
extern "C" void kernel_launch(void* const* d_in, const int* in_sizes, int n_in,
                              void* d_out, int out_size) {
    const int*   ids  = (const int*)  d_in[0];
    const float* emb  = (const float*)d_in[1];
    const float* ln_w = (const float*)d_in[2];
    const float* ln_b = (const float*)d_in[3];
    const float* Wg   = (const float*)d_in[4];
    const float* Rg   = (const float*)d_in[5];
    const float* bg   = (const float*)d_in[6];
    const float* gn_w = (const float*)d_in[7];
    const float* w1   = (const float*)d_in[8];
    const float* b1   = (const float*)d_in[9];
    const float* w2   = (const float*)d_in[10];
    const float* b2   = (const float*)d_in[11];
    float* out = (float*)d_out;

    cudaFuncSetAttribute(k_gemm, cudaFuncAttributeMaxDynamicSharedMemorySize, GEMM_SMEM);

    const int ROWS = kB * kL;                      // 65536 rows of 128

    k_wcvt<<<128, 256>>>(Wg);                      // both layers' W -> tf32
    k_embed_ln<<<ROWS / 8, 256>>>(ids, (const float4*)emb, ln_w, ln_b);

    // layer 0
    k_gemm<<<dim3(4, 512), 256, GEMM_SMEM>>>(0, bg);
    k_scan<<<128, 256>>>(Rg);
    k_gn<true><<<ROWS / 8, 256>>>(gn_w, ln_w + 128, ln_b + 128);

    // layer 1
    k_gemm<<<dim3(4, 512), 256, GEMM_SMEM>>>(1, bg + 512);
    k_scan<<<128, 256>>>(Rg + (size_t)4 * 4 * 32 * 32);
    k_gn<false><<<ROWS / 8, 256>>>(gn_w + 128, nullptr, nullptr);

    k_head<<<512, 128>>>(w1, b1, w2, b2, out);
}